// round 3
// baseline (speedup 1.0000x reference)
#include <cuda_runtime.h>
#include <stdint.h>
#include <math.h>

// ---------------------------------------------------------------------------
// Problem constants
// ---------------------------------------------------------------------------
#define NB      16       // batch
#define NCLS    80       // classes
#define NANCH   25200    // 80*80*3 + 40*40*3 + 20*20*3
#define TOPK    128      // NMS_TOPK
#define MAXOUT  100
#define SCORE_THR 0.25f
#define IOU_THR   0.45f

// ---------------------------------------------------------------------------
// Scratch (static __device__ arrays — no allocation allowed)
// ---------------------------------------------------------------------------
__device__ float g_scores[(size_t)NB * NCLS * NANCH];      // (B, C, N) class-major, 129 MB
__device__ float g_boxes[(size_t)NB * NANCH * 4];          // (B, N, 4)
__device__ float g_cls_scores[NB * NCLS * MAXOUT];         // per-class NMS output scores (-1 = invalid)
__device__ float g_cls_boxes[NB * NCLS * MAXOUT * 4];      // per-class NMS output boxes

__constant__ float c_anchor_w[9] = {10.f, 16.f, 33.f, 30.f, 62.f, 59.f, 116.f, 156.f, 373.f};
__constant__ float c_anchor_h[9] = {13.f, 30.f, 23.f, 61.f, 45.f, 119.f, 90.f, 198.f, 326.f};

__device__ __forceinline__ float sigm(float x) {
    return 1.0f / (1.0f + expf(-x));
}

// map any float to a monotone unsigned key
__device__ __forceinline__ unsigned fkeymap(float f) {
    unsigned u = __float_as_uint(f);
    return (u & 0x80000000u) ? ~u : (u | 0x80000000u);
}

// ---------------------------------------------------------------------------
// K1: decode boxes + write scores transposed (B, C, N)
// one thread per (b, anchor); 403200 threads
// ---------------------------------------------------------------------------
__global__ __launch_bounds__(256) void decode_kernel(
    const float* __restrict__ p3, const float* __restrict__ p4, const float* __restrict__ p5)
{
    int t = blockIdx.x * 256 + threadIdx.x;      // grid sized exactly: 1575*256 = 403200
    int b = t / NANCH;
    int n = t - b * NANCH;

    const float* base; int W; float stride; int rem; int abase;
    if (n < 19200)      { base = p3; W = 80; stride = 8.f;  rem = n;         abase = 0; }
    else if (n < 24000) { base = p4; W = 40; stride = 16.f; rem = n - 19200; abase = 3; }
    else                { base = p5; W = 20; stride = 32.f; rem = n - 24000; abase = 6; }

    int a  = rem % 3;
    int hw = rem / 3;
    int y  = hw / W;
    int x  = hw - y * W;

    const float* ptr = base + ((size_t)b * W * W + hw) * 255 + a * 85;

    float l0 = ptr[0], l1 = ptr[1], l2 = ptr[2], l3 = ptr[3], l4 = ptr[4];

    float cx = (sigm(l0) + (float)x) * stride;
    float cy = (sigm(l1) + (float)y) * stride;
    float w  = expf(l2) * c_anchor_w[abase + a];
    float h  = expf(l3) * c_anchor_h[abase + a];

    float* bo = g_boxes + (size_t)t * 4;        // t == b*NANCH + n
    bo[0] = cx - w * 0.5f;
    bo[1] = cy - h * 0.5f;
    bo[2] = cx + w * 0.5f;
    bo[3] = cy + h * 0.5f;

    float obj = sigm(l4);
    float* srow = g_scores + (size_t)b * NCLS * NANCH + n;
    #pragma unroll 4
    for (int c = 0; c < NCLS; ++c) {
        srow[(size_t)c * NANCH] = obj * sigm(ptr[5 + c]);   // coalesced store per c
    }
}

// ---------------------------------------------------------------------------
// K2: per (b, class): top-128 select (exact, jax tie-break) + NMS + top-100
// one block of 256 threads per task; 1280 blocks
// ---------------------------------------------------------------------------
__global__ __launch_bounds__(256) void topk_nms_kernel()
{
    const int task = blockIdx.x;
    const int b = task / NCLS;
    const int c = task - b * NCLS;
    const int tid = threadIdx.x;

    const float* __restrict__ srow = g_scores + ((size_t)b * NCLS + c) * NANCH;

    // --- per-thread top-16 (sorted desc) over strided slice ---
    unsigned long long r[16];
    #pragma unroll
    for (int j = 0; j < 16; ++j) r[j] = 0ull;

    for (int n = tid; n < NANCH; n += 256) {
        float s = srow[n];
        if (s > SCORE_THR) {
            // positive float bits are order-preserving as uint; inv index => index-asc tie-break
            unsigned long long key =
                ((unsigned long long)__float_as_uint(s) << 32) | (unsigned)(0x00FFFFFF - n);
            if (key > r[15]) {
                r[15] = key;
                #pragma unroll
                for (int j = 15; j > 0; --j) {
                    if (r[j] > r[j - 1]) { unsigned long long tmp = r[j]; r[j] = r[j-1]; r[j-1] = tmp; }
                }
            }
        }
    }

    __shared__ unsigned long long s_keys[4096];
    #pragma unroll
    for (int j = 0; j < 16; ++j) s_keys[tid * 16 + j] = r[j];
    __syncthreads();

    // --- bitonic sort 4096 keys, descending ---
    for (int k = 2; k <= 4096; k <<= 1) {
        for (int j = k >> 1; j > 0; j >>= 1) {
            for (int i = tid; i < 4096; i += 256) {
                int l = i ^ j;
                if (l > i) {
                    unsigned long long a = s_keys[i];
                    unsigned long long bb = s_keys[l];
                    bool desc = ((i & k) == 0);
                    if ((a < bb) == desc) { s_keys[i] = bb; s_keys[l] = a; }
                }
            }
            __syncthreads();
        }
    }

    // --- gather top-128 candidates ---
    __shared__ float s_bx1[TOPK], s_by1[TOPK], s_bx2[TOPK], s_by2[TOPK];
    __shared__ float s_area[TOPK], s_score[TOPK];
    __shared__ unsigned s_sup[TOPK][4];
    __shared__ unsigned s_keep[4];
    __shared__ unsigned s_vball[4];

    if (tid < MAXOUT) g_cls_scores[task * MAXOUT + tid] = -1.0f;   // default invalid

    if (tid < TOPK) {
        unsigned long long key = s_keys[tid];
        float s = __uint_as_float((unsigned)(key >> 32));
        int n = 0x00FFFFFF - (int)(unsigned)(key & 0xFFFFFFFFull);
        if (!(s > 0.f)) n = 0;     // padding slot: any in-range box, never used
        s_score[tid] = s;
        const float* bp = g_boxes + ((size_t)b * NANCH + n) * 4;
        float x1 = bp[0], y1 = bp[1], x2 = bp[2], y2 = bp[3];
        s_bx1[tid] = x1; s_by1[tid] = y1; s_bx2[tid] = x2; s_by2[tid] = y2;
        s_area[tid] = (x2 - x1) * (y2 - y1);
    }
    __syncthreads();

    // --- suppression bitmask: s_sup[i][w] bit t set iff j=32w+t > i and iou(i,j) > thr ---
    for (int wi = tid; wi < TOPK * 4; wi += 256) {
        int i = wi >> 2;
        int w = wi & 3;
        float ax1 = s_bx1[i], ay1 = s_by1[i], ax2 = s_bx2[i], ay2 = s_by2[i], aa = s_area[i];
        unsigned m = 0;
        #pragma unroll 4
        for (int tt = 0; tt < 32; ++tt) {
            int j = (w << 5) + tt;
            if (j > i) {
                float iw = fmaxf(fminf(ax2, s_bx2[j]) - fmaxf(ax1, s_bx1[j]), 0.f);
                float ih = fmaxf(fminf(ay2, s_by2[j]) - fmaxf(ay1, s_by1[j]), 0.f);
                float inter = iw * ih;
                float iou = inter / (aa + s_area[j] - inter + 1e-9f);
                if (iou > IOU_THR) m |= (1u << tt);
            }
        }
        s_sup[i][w] = m;
    }
    __syncthreads();

    // --- sequential NMS scan (the lax.scan) on 128-bit bitmask ---
    if (tid == 0) {
        unsigned k0 = 0xFFFFFFFFu, k1 = 0xFFFFFFFFu, k2 = 0xFFFFFFFFu, k3 = 0xFFFFFFFFu;
        for (int i = 0; i < TOPK; ++i) {
            unsigned kw = (i < 32) ? k0 : (i < 64) ? k1 : (i < 96) ? k2 : k3;
            if (((kw >> (i & 31)) & 1u) && (s_score[i] > 0.f)) {
                k0 &= ~s_sup[i][0]; k1 &= ~s_sup[i][1]; k2 &= ~s_sup[i][2]; k3 &= ~s_sup[i][3];
            }
        }
        s_keep[0] = k0; s_keep[1] = k1; s_keep[2] = k2; s_keep[3] = k3;
    }
    __syncthreads();

    // --- compact valid survivors in order -> per-class top-100 ---
    bool valid = false;
    if (tid < TOPK) {
        valid = (((s_keep[tid >> 5] >> (tid & 31)) & 1u) != 0) && (s_score[tid] > 0.f);
        unsigned bal = __ballot_sync(0xFFFFFFFFu, valid);
        if ((tid & 31) == 0) s_vball[tid >> 5] = bal;
    }
    __syncthreads();

    if (tid < TOPK && valid) {
        int w = tid >> 5;
        int pos = __popc(s_vball[w] & ((1u << (tid & 31)) - 1u));
        #pragma unroll
        for (int q = 0; q < 4; ++q) if (q < w) pos += __popc(s_vball[q]);
        if (pos < MAXOUT) {
            size_t o = (size_t)task * MAXOUT + pos;
            g_cls_scores[o] = s_score[tid];
            float* ob = g_cls_boxes + o * 4;
            ob[0] = s_bx1[tid]; ob[1] = s_by1[tid]; ob[2] = s_bx2[tid]; ob[3] = s_by2[tid];
        }
    }
}

// ---------------------------------------------------------------------------
// K3: per-image top-100 over 80 sorted per-class lists (exact streaming merge)
// one warp per image
// ---------------------------------------------------------------------------
__global__ __launch_bounds__(32) void final_kernel(float* __restrict__ out)
{
    int b = blockIdx.x;
    int lane = threadIdx.x;

    int ptrq[3];
    unsigned long long hk[3];
    #pragma unroll
    for (int q = 0; q < 3; ++q) {
        int c = lane + 32 * q;
        ptrq[q] = 0;
        if (c < NCLS) {
            float s = g_cls_scores[(b * NCLS + c) * MAXOUT];
            unsigned flat = (unsigned)(c * MAXOUT);
            hk[q] = ((unsigned long long)fkeymap(s) << 32) | (unsigned)(0xFFFFu - flat);
        } else hk[q] = 0ull;
    }

    int nval = 0;
    for (int rr = 0; rr < MAXOUT; ++rr) {
        unsigned long long best = hk[0]; int bq = 0;
        if (hk[1] > best) { best = hk[1]; bq = 1; }
        if (hk[2] > best) { best = hk[2]; bq = 2; }

        unsigned long long gmax = best;
        #pragma unroll
        for (int off = 16; off > 0; off >>= 1) {
            unsigned long long o = __shfl_xor_sync(0xFFFFFFFFu, gmax, off);
            if (o > gmax) gmax = o;
        }
        bool val = ((unsigned)(gmax >> 32)) > 0x80000000u;   // score > 0

        if (best == gmax) {   // unique winner when gmax != 0 (flat index in key)
            int c = lane + 32 * bq;
            int k = ptrq[bq];
            float* ob = out + ((size_t)b * MAXOUT + rr) * 4;
            if (val) {
                size_t o = (size_t)(b * NCLS + c) * MAXOUT + k;
                float s = g_cls_scores[o];
                const float* bp = g_cls_boxes + o * 4;
                ob[0] = bp[0]; ob[1] = bp[1]; ob[2] = bp[2]; ob[3] = bp[3];
                out[NB * MAXOUT * 4 + b * MAXOUT + rr] = s;
                out[NB * MAXOUT * 5 + b * MAXOUT + rr] = (float)c;
            } else {
                ob[0] = 0.f; ob[1] = 0.f; ob[2] = 0.f; ob[3] = 0.f;
                out[NB * MAXOUT * 4 + b * MAXOUT + rr] = 0.f;
                out[NB * MAXOUT * 5 + b * MAXOUT + rr] = 0.f;
            }
            k++;
            ptrq[bq] = k;
            if (k < MAXOUT && c < NCLS) {
                float s = g_cls_scores[(b * NCLS + c) * MAXOUT + k];
                unsigned flat = (unsigned)(c * MAXOUT + k);
                hk[bq] = ((unsigned long long)fkeymap(s) << 32) | (unsigned)(0xFFFFu - flat);
            } else hk[bq] = 0ull;
        }
        nval += val ? 1 : 0;
    }
    if (lane == 0) out[NB * MAXOUT * 6 + b] = (float)nval;
}

// ---------------------------------------------------------------------------
// Entry point
// ---------------------------------------------------------------------------
extern "C" void kernel_launch(void* const* d_in, const int* in_sizes, int n_in,
                              void* d_out, int out_size)
{
    // identify inputs by element count (robust to ordering)
    const float* p3 = nullptr; const float* p4 = nullptr; const float* p5 = nullptr;
    for (int i = 0; i < n_in; ++i) {
        if      (in_sizes[i] == 16 * 80 * 80 * 255) p3 = (const float*)d_in[i];
        else if (in_sizes[i] == 16 * 40 * 40 * 255) p4 = (const float*)d_in[i];
        else if (in_sizes[i] == 16 * 20 * 20 * 255) p5 = (const float*)d_in[i];
    }
    float* out = (float*)d_out;

    decode_kernel<<<(NB * NANCH) / 256, 256>>>(p3, p4, p5);   // 1575 blocks
    topk_nms_kernel<<<NB * NCLS, 256>>>();                    // 1280 blocks
    final_kernel<<<NB, 32>>>(out);                            // 16 warps
}

// round 4
// speedup vs baseline: 2.5963x; 2.5963x over previous
#include <cuda_runtime.h>
#include <stdint.h>
#include <math.h>

// ---------------------------------------------------------------------------
// Problem constants
// ---------------------------------------------------------------------------
#define NB      16       // batch
#define NCLS    80       // classes
#define NANCH   25200    // 80*80*3 + 40*40*3 + 20*20*3
#define TOPK    128      // NMS_TOPK
#define MAXOUT  100
#define SCORE_THR 0.25f
#define IOU_THR   0.45f

#define K1_CELLS   16    // cells per block (divides 6400, 1600, 400, and 8400)
#define K1_THREADS 128
#define CAND_MAX   2048

// ---------------------------------------------------------------------------
// Scratch (static __device__ arrays — no allocation allowed)
// ---------------------------------------------------------------------------
__device__ float g_scores[(size_t)NB * NCLS * NANCH];      // (B, C, N) class-major
__device__ float g_boxes[(size_t)NB * NANCH * 4];          // (B, N, 4)
__device__ float g_cls_scores[NB * NCLS * MAXOUT];         // per-class NMS scores (-1 = invalid)
__device__ float g_cls_boxes[NB * NCLS * MAXOUT * 4];      // per-class NMS boxes

__constant__ float c_anchor_w[9] = {10.f, 16.f, 33.f, 30.f, 62.f, 59.f, 116.f, 156.f, 373.f};
__constant__ float c_anchor_h[9] = {13.f, 30.f, 23.f, 61.f, 45.f, 119.f, 90.f, 198.f, 326.f};

__device__ __forceinline__ float sigm(float x) {
    return 1.0f / (1.0f + expf(-x));
}

// map any float to a monotone unsigned key
__device__ __forceinline__ unsigned fkeymap(float f) {
    unsigned u = __float_as_uint(f);
    return (u & 0x80000000u) ? ~u : (u | 0x80000000u);
}

// ---------------------------------------------------------------------------
// K1: decode + score transpose, shared-staged for coalesced loads.
// Block = 128 threads handles 16 cells (48 anchors, 4080 input floats).
// Grid = NB*8400/16 = 8400 blocks.
// ---------------------------------------------------------------------------
__global__ __launch_bounds__(K1_THREADS) void decode_kernel(
    const float* __restrict__ p3, const float* __restrict__ p4, const float* __restrict__ p5)
{
    __shared__ float s_in[K1_CELLS * 255];     // 16320 B, contiguous input slab
    __shared__ float s_obj[K1_CELLS * 3];

    const int tid = threadIdx.x;
    int cell0 = blockIdx.x * K1_CELLS;         // global cell index (B x 8400 cells)
    int b  = cell0 / 8400;
    int r0 = cell0 - b * 8400;                 // image-local cell

    const float* src; int W; float strd; int abase; int n0; int hw0;
    if (r0 < 6400)      { hw0 = r0;        W = 80; strd = 8.f;  abase = 0; src = p3 + ((size_t)b * 6400 + hw0) * 255; n0 = hw0 * 3; }
    else if (r0 < 8000) { hw0 = r0 - 6400; W = 40; strd = 16.f; abase = 3; src = p4 + ((size_t)b * 1600 + hw0) * 255; n0 = 19200 + hw0 * 3; }
    else                { hw0 = r0 - 8000; W = 20; strd = 32.f; abase = 6; src = p5 + ((size_t)b *  400 + hw0) * 255; n0 = 24000 + hw0 * 3; }

    // stage: fully coalesced contiguous copy
    #pragma unroll 4
    for (int i = tid; i < K1_CELLS * 255; i += K1_THREADS) s_in[i] = src[i];
    __syncthreads();

    // decode 48 anchors (threads 0..47); anchor j -> shared offset 85*j
    if (tid < K1_CELLS * 3) {
        int cl = tid / 3;
        int a  = tid - cl * 3;
        int hw = hw0 + cl;
        int y  = hw / W;
        int x  = hw - y * W;
        const float* q = s_in + tid * 85;      // cl*255 + a*85 == 85*tid

        float cx = (sigm(q[0]) + (float)x) * strd;
        float cy = (sigm(q[1]) + (float)y) * strd;
        float w  = expf(q[2]) * c_anchor_w[abase + a];
        float h  = expf(q[3]) * c_anchor_h[abase + a];

        float* bo = g_boxes + ((size_t)b * NANCH + n0 + tid) * 4;
        bo[0] = cx - w * 0.5f;
        bo[1] = cy - h * 0.5f;
        bo[2] = cx + w * 0.5f;
        bo[3] = cy + h * 0.5f;

        s_obj[tid] = sigm(q[4]);
    }
    __syncthreads();

    // scores: 48 anchors x 80 classes = 3840 ops; stores coalesced in 48-float runs
    const int NA = K1_CELLS * 3;               // 48
    #pragma unroll 5
    for (int w = 0; w < (NA * NCLS) / K1_THREADS; ++w) {   // 30 iterations
        int idx = w * K1_THREADS + tid;
        int c = idx / NA;
        int j = idx - c * NA;
        float v = s_obj[j] * sigm(s_in[j * 85 + 5 + c]);   // 85-word stride: conflict-free
        g_scores[((size_t)b * NCLS + c) * NANCH + n0 + j] = v;
    }
}

// ---------------------------------------------------------------------------
// K2: per (b, class): exact top-128 via histogram threshold + small sort + NMS
// one block of 256 threads per task; 1280 blocks
// ---------------------------------------------------------------------------
__global__ __launch_bounds__(256) void topk_nms_kernel()
{
    const int task = blockIdx.x;
    const int b = task / NCLS;
    const int c = task - b * NCLS;
    const int tid = threadIdx.x;

    const float* __restrict__ srow = g_scores + ((size_t)b * NCLS + c) * NANCH;

    __shared__ unsigned long long s_cand[CAND_MAX];        // 16 KB; aliased as hist in pass A
    unsigned* hist = (unsigned*)s_cand;                    // 4096 buckets
    __shared__ unsigned s_csum[256];
    __shared__ unsigned s_T, s_cnt;

    // --- pass A: histogram of score bits (scores in (0.25, 1) span exactly 2^24 bit codes) ---
    for (int i = tid; i < 4096; i += 256) hist[i] = 0;
    __syncthreads();

    for (int n = tid; n < NANCH; n += 256) {
        float s = srow[n];
        if (s > SCORE_THR) {
            unsigned bk = min((__float_as_uint(s) - 0x3E800000u) >> 12, 4095u);
            atomicAdd(&hist[bk], 1u);
        }
    }
    __syncthreads();

    // --- per-thread chunk sums (16 buckets each) ---
    unsigned sum = 0;
    #pragma unroll
    for (int k = 0; k < 16; ++k) sum += hist[tid * 16 + k];
    s_csum[tid] = sum;
    __syncthreads();

    // --- thread 0: find threshold bucket T (suffix count first >= 128) ---
    if (tid == 0) {
        unsigned acc = 0;
        int ch;
        for (ch = 255; ch >= 0; --ch) {
            if (acc + s_csum[ch] >= TOPK) break;
            acc += s_csum[ch];
        }
        unsigned T = 0;
        if (ch >= 0) {
            for (int q = ch * 16 + 15; q >= ch * 16; --q) {
                acc += hist[q];
                if (acc >= TOPK) { T = (unsigned)q; break; }
            }
        }
        s_T = T;
        s_cnt = 0;
    }
    __syncthreads();

    // --- pass B: collect candidate keys with bucket >= T (overwrites hist region) ---
    unsigned T = s_T;
    for (int n = tid; n < NANCH; n += 256) {
        float s = srow[n];
        if (s > SCORE_THR) {
            unsigned ub = __float_as_uint(s);
            unsigned bk = min((ub - 0x3E800000u) >> 12, 4095u);
            if (bk >= T) {
                unsigned p = atomicAdd(&s_cnt, 1u);
                if (p < CAND_MAX)
                    s_cand[p] = ((unsigned long long)ub << 32) | (unsigned)(0x00FFFFFF - n);
            }
        }
    }
    __syncthreads();

    int cnt = (int)min(s_cnt, (unsigned)CAND_MAX);
    int P = TOPK;
    while (P < cnt) P <<= 1;                   // power-of-two sort size >= max(cnt, 128)
    for (int i = cnt + tid; i < P; i += 256) s_cand[i] = 0ull;
    __syncthreads();

    // --- bitonic sort P keys descending (P typically 128 or 256) ---
    for (int k = 2; k <= P; k <<= 1) {
        for (int j = k >> 1; j > 0; j >>= 1) {
            for (int i = tid; i < P; i += 256) {
                int l = i ^ j;
                if (l > i) {
                    unsigned long long a  = s_cand[i];
                    unsigned long long bb = s_cand[l];
                    bool desc = ((i & k) == 0);
                    if ((a < bb) == desc) { s_cand[i] = bb; s_cand[l] = a; }
                }
            }
            __syncthreads();
        }
    }

    // --- gather top-128 candidates ---
    __shared__ float s_bx1[TOPK], s_by1[TOPK], s_bx2[TOPK], s_by2[TOPK];
    __shared__ float s_area[TOPK], s_score[TOPK];
    __shared__ unsigned s_sup[TOPK][4];
    __shared__ unsigned s_keep[4];
    __shared__ unsigned s_vball[4];

    if (tid < MAXOUT) g_cls_scores[task * MAXOUT + tid] = -1.0f;   // default invalid

    if (tid < TOPK) {
        unsigned long long key = s_cand[tid];
        float s = __uint_as_float((unsigned)(key >> 32));
        int n = 0x00FFFFFF - (int)(unsigned)(key & 0xFFFFFFFFull);
        if (!(s > 0.f)) n = 0;     // padding slot: any in-range box, never used
        s_score[tid] = s;
        const float* bp = g_boxes + ((size_t)b * NANCH + n) * 4;
        float x1 = bp[0], y1 = bp[1], x2 = bp[2], y2 = bp[3];
        s_bx1[tid] = x1; s_by1[tid] = y1; s_bx2[tid] = x2; s_by2[tid] = y2;
        s_area[tid] = (x2 - x1) * (y2 - y1);
    }
    __syncthreads();

    // --- suppression bitmask: s_sup[i][w] bit t set iff j=32w+t > i and iou(i,j) > thr ---
    for (int wi = tid; wi < TOPK * 4; wi += 256) {
        int i = wi >> 2;
        int w = wi & 3;
        float ax1 = s_bx1[i], ay1 = s_by1[i], ax2 = s_bx2[i], ay2 = s_by2[i], aa = s_area[i];
        unsigned m = 0;
        #pragma unroll 4
        for (int tt = 0; tt < 32; ++tt) {
            int j = (w << 5) + tt;
            if (j > i) {
                float iw = fmaxf(fminf(ax2, s_bx2[j]) - fmaxf(ax1, s_bx1[j]), 0.f);
                float ih = fmaxf(fminf(ay2, s_by2[j]) - fmaxf(ay1, s_by1[j]), 0.f);
                float inter = iw * ih;
                float iou = inter / (aa + s_area[j] - inter + 1e-9f);
                if (iou > IOU_THR) m |= (1u << tt);
            }
        }
        s_sup[i][w] = m;
    }
    __syncthreads();

    // --- sequential NMS scan (the lax.scan) on 128-bit bitmask ---
    if (tid == 0) {
        unsigned k0 = 0xFFFFFFFFu, k1 = 0xFFFFFFFFu, k2 = 0xFFFFFFFFu, k3 = 0xFFFFFFFFu;
        for (int i = 0; i < TOPK; ++i) {
            unsigned kw = (i < 32) ? k0 : (i < 64) ? k1 : (i < 96) ? k2 : k3;
            if (((kw >> (i & 31)) & 1u) && (s_score[i] > 0.f)) {
                k0 &= ~s_sup[i][0]; k1 &= ~s_sup[i][1]; k2 &= ~s_sup[i][2]; k3 &= ~s_sup[i][3];
            }
        }
        s_keep[0] = k0; s_keep[1] = k1; s_keep[2] = k2; s_keep[3] = k3;
    }
    __syncthreads();

    // --- compact valid survivors in order -> per-class top-100 ---
    bool valid = false;
    if (tid < TOPK) {
        valid = (((s_keep[tid >> 5] >> (tid & 31)) & 1u) != 0) && (s_score[tid] > 0.f);
        unsigned bal = __ballot_sync(0xFFFFFFFFu, valid);
        if ((tid & 31) == 0) s_vball[tid >> 5] = bal;
    }
    __syncthreads();

    if (tid < TOPK && valid) {
        int w = tid >> 5;
        int pos = __popc(s_vball[w] & ((1u << (tid & 31)) - 1u));
        #pragma unroll
        for (int q = 0; q < 4; ++q) if (q < w) pos += __popc(s_vball[q]);
        if (pos < MAXOUT) {
            size_t o = (size_t)task * MAXOUT + pos;
            g_cls_scores[o] = s_score[tid];
            float* ob = g_cls_boxes + o * 4;
            ob[0] = s_bx1[tid]; ob[1] = s_by1[tid]; ob[2] = s_bx2[tid]; ob[3] = s_by2[tid];
        }
    }
}

// ---------------------------------------------------------------------------
// K3: per-image top-100 over 80 sorted per-class lists (exact streaming merge)
// one warp per image
// ---------------------------------------------------------------------------
__global__ __launch_bounds__(32) void final_kernel(float* __restrict__ out)
{
    int b = blockIdx.x;
    int lane = threadIdx.x;

    int ptrq[3];
    unsigned long long hk[3];
    #pragma unroll
    for (int q = 0; q < 3; ++q) {
        int c = lane + 32 * q;
        ptrq[q] = 0;
        if (c < NCLS) {
            float s = g_cls_scores[(b * NCLS + c) * MAXOUT];
            unsigned flat = (unsigned)(c * MAXOUT);
            hk[q] = ((unsigned long long)fkeymap(s) << 32) | (unsigned)(0xFFFFu - flat);
        } else hk[q] = 0ull;
    }

    int nval = 0;
    for (int rr = 0; rr < MAXOUT; ++rr) {
        unsigned long long best = hk[0]; int bq = 0;
        if (hk[1] > best) { best = hk[1]; bq = 1; }
        if (hk[2] > best) { best = hk[2]; bq = 2; }

        unsigned long long gmax = best;
        #pragma unroll
        for (int off = 16; off > 0; off >>= 1) {
            unsigned long long o = __shfl_xor_sync(0xFFFFFFFFu, gmax, off);
            if (o > gmax) gmax = o;
        }
        bool val = ((unsigned)(gmax >> 32)) > 0x80000000u;   // score > 0

        if (best == gmax) {   // unique winner (flat index embedded in key)
            int c = lane + 32 * bq;
            int k = ptrq[bq];
            float* ob = out + ((size_t)b * MAXOUT + rr) * 4;
            if (val) {
                size_t o = (size_t)(b * NCLS + c) * MAXOUT + k;
                float s = g_cls_scores[o];
                const float* bp = g_cls_boxes + o * 4;
                ob[0] = bp[0]; ob[1] = bp[1]; ob[2] = bp[2]; ob[3] = bp[3];
                out[NB * MAXOUT * 4 + b * MAXOUT + rr] = s;
                out[NB * MAXOUT * 5 + b * MAXOUT + rr] = (float)c;
            } else {
                ob[0] = 0.f; ob[1] = 0.f; ob[2] = 0.f; ob[3] = 0.f;
                out[NB * MAXOUT * 4 + b * MAXOUT + rr] = 0.f;
                out[NB * MAXOUT * 5 + b * MAXOUT + rr] = 0.f;
            }
            k++;
            ptrq[bq] = k;
            if (k < MAXOUT && c < NCLS) {
                float s = g_cls_scores[(b * NCLS + c) * MAXOUT + k];
                unsigned flat = (unsigned)(c * MAXOUT + k);
                hk[bq] = ((unsigned long long)fkeymap(s) << 32) | (unsigned)(0xFFFFu - flat);
            } else hk[bq] = 0ull;
        }
        nval += val ? 1 : 0;
    }
    if (lane == 0) out[NB * MAXOUT * 6 + b] = (float)nval;
}

// ---------------------------------------------------------------------------
// Entry point
// ---------------------------------------------------------------------------
extern "C" void kernel_launch(void* const* d_in, const int* in_sizes, int n_in,
                              void* d_out, int out_size)
{
    // identify inputs by element count (robust to ordering)
    const float* p3 = nullptr; const float* p4 = nullptr; const float* p5 = nullptr;
    for (int i = 0; i < n_in; ++i) {
        if      (in_sizes[i] == 16 * 80 * 80 * 255) p3 = (const float*)d_in[i];
        else if (in_sizes[i] == 16 * 40 * 40 * 255) p4 = (const float*)d_in[i];
        else if (in_sizes[i] == 16 * 20 * 20 * 255) p5 = (const float*)d_in[i];
    }
    float* out = (float*)d_out;

    decode_kernel<<<(NB * 8400) / K1_CELLS, K1_THREADS>>>(p3, p4, p5);  // 8400 blocks
    topk_nms_kernel<<<NB * NCLS, 256>>>();                              // 1280 blocks
    final_kernel<<<NB, 32>>>(out);                                      // 16 warps
}